// round 15
// baseline (speedup 1.0000x reference)
#include <cuda_runtime.h>

#define BATCH   64
#define N       128
#define LAYERS  128
#define PAIRS   64
#define STEEP   10.0f
#define INV_PI  0.318309886183790671538f
#define FULL    0xffffffffu

// coefficient arrays written by producer, read by consumer:
// g_alphas4[b][L2][lane] = {al0, al1, am, b1z}; g_bpz[b][L2][lane] = bpz
__device__ float4 g_alphas4[BATCH * (LAYERS / 2) * 32];
__device__ float  g_bpz   [BATCH * (LAYERS / 2) * 32];

// fast soft-compare alpha: atan(STEEP*(b-a))/pi + 0.5, abs err ~1e-5
static __device__ __forceinline__ float fast_alpha(float a, float b) {
    float y  = STEEP * (b - a);
    float ay = fabsf(y);
    bool big = ay > 1.0f;
    float t  = big ? __fdividef(1.0f, y) : y;
    float z  = t * t;
    float p  =          -0.0117212f;
    p = fmaf(p, z,  0.05265332f);
    p = fmaf(p, z, -0.11643287f);
    p = fmaf(p, z,  0.19354346f);
    p = fmaf(p, z, -0.33262347f);
    p = fmaf(p, z,  0.99997726f);
    p = p * t;                                   // ~atan(t)
    float r = big ? (copysignf(1.57079632679f, y) - p) : p;
    return fmaf(r, INV_PI, 0.5f);
}

// ---------------------------------------------------------------------------
// Kernel A: one warp per batch, x in registers (lane l owns x[4l..4l+3]).
// Serial 128-layer chain with fast_alpha on the critical path. Also emits the
// consumer-ready coefficients {al0, al1, am, b1z} + bpz (edge-zeroed).
// ---------------------------------------------------------------------------
__global__ __launch_bounds__(32) void alpha_kernel(const float* __restrict__ in,
                                                   float* __restrict__ out_x) {
    const int b = blockIdx.x;
    const int l = threadIdx.x;

    const float4 xi = ((const float4*)(in + b * N))[l];
    float x0 = xi.x, x1 = xi.y, x2 = xi.z, x3 = xi.w;

    float4* aout = g_alphas4 + (size_t)b * (LAYERS / 2) * 32;
    float*  bout = g_bpz     + (size_t)b * (LAYERS / 2) * 32;

    #pragma unroll 2
    for (int L = 0; L < LAYERS; L += 2) {
        // ---- even layer: pairs (4l,4l+1), (4l+2,4l+3) intra-lane ----
        float d0 = x0 - x1;
        float d1 = x2 - x3;
        float al0 = fast_alpha(x0, x1);
        float al1 = fast_alpha(x2, x3);
        float n0 = fmaf(al0, d0, x1);
        float n1 = fmaf(-al0, d0, x0);
        float n2 = fmaf(al1, d1, x3);
        float n3 = fmaf(-al1, d1, x2);
        x0 = n0; x1 = n1; x2 = n2; x3 = n3;

        // ---- odd layer: (4l+1,4l+2) intra; (4l+3,4l+4) cross ----
        float bn = __shfl_down_sync(FULL, x0, 1); // next lane's x0 (old)
        float pa = __shfl_up_sync  (FULL, x3, 1); // prev lane's x3 (old)
        float dm = x1 - x2;
        float am = fast_alpha(x1, x2);
        float ac = fast_alpha(x3, bn);
        float alp = __shfl_up_sync(FULL, ac, 1);
        float b1z = (l == 31) ? 0.0f : (1.0f - ac);
        float bpz = (l == 0)  ? 0.0f : (1.0f - alp);
        float nx1 = fmaf(am, dm, x2);
        float nx2 = fmaf(-am, dm, x1);
        x3 = fmaf(b1z, bn - x3, x3);   // no-op on lane 31
        x0 = fmaf(bpz, pa - x0, x0);   // no-op on lane 0
        x1 = nx1; x2 = nx2;

        aout[(L >> 1) * 32 + l] = make_float4(al0, al1, am, b1z);
        bout[(L >> 1) * 32 + l] = bpz;
    }

    ((float4*)(out_x + b * N))[l] = make_float4(x0, x1, x2, x3);
}

// ---------------------------------------------------------------------------
// Kernel B: each warp owns 2 rows of X, register-resident (lane l holds
// cols 4l..4l+3 of both rows). Coefficients fully precomputed by producer:
// 1 LDS.128 + 1 LDS.32 per warp per 2 layers, zero coefficient ALU.
// grid = BATCH*8 CTAs x 256 threads (R9's proven occupancy point).
// ---------------------------------------------------------------------------
__global__ __launch_bounds__(256) void mix_kernel(float* __restrict__ out_X) {
    __shared__ float4 As[(LAYERS / 2) * 32];   // 32 KB
    __shared__ float  Bs[(LAYERS / 2) * 32];   //  8 KB

    const int b   = blockIdx.x >> 3;
    const int grp = blockIdx.x & 7;
    const int tid = threadIdx.x;

    {
        const float4* src = g_alphas4 + (size_t)b * (LAYERS / 2) * 32;
        #pragma unroll
        for (int i = 0; i < (LAYERS / 2) * 32 / 256; ++i)
            As[tid + i * 256] = src[tid + i * 256];
        const float4* srcb = (const float4*)(g_bpz + (size_t)b * (LAYERS / 2) * 32);
        float4* dstb = (float4*)Bs;
        #pragma unroll
        for (int i = 0; i < (LAYERS / 2) * 32 / 4 / 256; ++i)
            dstb[tid + i * 256] = srcb[tid + i * 256];
    }
    __syncthreads();

    const int warp = tid >> 5;
    const int lane = tid & 31;
    const int row0 = grp * 16 + warp * 2;

    // identity rows row0, row0+1 (suffix a = row0, b = row0+1)
    float c0a = (row0 == 4 * lane + 0) ? 1.0f : 0.0f;
    float c1a = (row0 == 4 * lane + 1) ? 1.0f : 0.0f;
    float c2a = (row0 == 4 * lane + 2) ? 1.0f : 0.0f;
    float c3a = (row0 == 4 * lane + 3) ? 1.0f : 0.0f;
    float c0b = (row0 + 1 == 4 * lane + 0) ? 1.0f : 0.0f;
    float c1b = (row0 + 1 == 4 * lane + 1) ? 1.0f : 0.0f;
    float c2b = (row0 + 1 == 4 * lane + 2) ? 1.0f : 0.0f;
    float c3b = (row0 + 1 == 4 * lane + 3) ? 1.0f : 0.0f;

    #pragma unroll 4
    for (int L2 = 0; L2 < LAYERS / 2; ++L2) {
        float4 a  = As[L2 * 32 + lane];   // {al0, al1, am, b1z}
        float bpz = Bs[L2 * 32 + lane];

        // ---- even layer ----
        {
            float d0 = c0a - c1a;
            float t0 = fmaf(a.x, d0, c1a);
            float t1 = fmaf(-a.x, d0, c0a);
            float d1 = c2a - c3a;
            float t2 = fmaf(a.y, d1, c3a);
            float t3 = fmaf(-a.y, d1, c2a);
            c0a = t0; c1a = t1; c2a = t2; c3a = t3;
        }
        {
            float d0 = c0b - c1b;
            float t0 = fmaf(a.x, d0, c1b);
            float t1 = fmaf(-a.x, d0, c0b);
            float d1 = c2b - c3b;
            float t2 = fmaf(a.y, d1, c3b);
            float t3 = fmaf(-a.y, d1, c2b);
            c0b = t0; c1b = t1; c2b = t2; c3b = t3;
        }

        // ---- odd layer ----
        {
            float nb = __shfl_down_sync(FULL, c0a, 1);
            float pa = __shfl_up_sync  (FULL, c3a, 1);
            float dm = c1a - c2a;
            float n1 = fmaf(a.z, dm, c2a);
            float n2 = fmaf(-a.z, dm, c1a);
            c3a = fmaf(a.w, nb - c3a, c3a);   // no-op lane 31 (b1z = 0)
            c0a = fmaf(bpz, pa - c0a, c0a);   // no-op lane 0  (bpz = 0)
            c1a = n1; c2a = n2;
        }
        {
            float nb = __shfl_down_sync(FULL, c0b, 1);
            float pa = __shfl_up_sync  (FULL, c3b, 1);
            float dm = c1b - c2b;
            float n1 = fmaf(a.z, dm, c2b);
            float n2 = fmaf(-a.z, dm, c1b);
            c3b = fmaf(a.w, nb - c3b, c3b);
            c0b = fmaf(bpz, pa - c0b, c0b);
            c1b = n1; c2b = n2;
        }
    }

    float* outb = out_X + (size_t)b * N * N;
    ((float4*)(outb + row0 * N))[lane]       = make_float4(c0a, c1a, c2a, c3a);
    ((float4*)(outb + (row0 + 1) * N))[lane] = make_float4(c0b, c1b, c2b, c3b);
}

extern "C" void kernel_launch(void* const* d_in, const int* in_sizes, int n_in,
                              void* d_out, int out_size) {
    (void)in_sizes; (void)n_in; (void)out_size;
    const float* vec = (const float*)d_in[0];
    float* out = (float*)d_out;

    // output layout: [x (64*128)] then [X (64*128*128)]
    alpha_kernel<<<BATCH, 32>>>(vec, out);
    mix_kernel<<<BATCH * 8, 256>>>(out + BATCH * N);
}